// round 3
// baseline (speedup 1.0000x reference)
#include <cuda_runtime.h>
#include <cstdint>

// ---------------------------------------------------------------------------
// PointAggregator fused forward, fp32, B=1 R=4096 SR=40 K=8 F=32 H=256
//   N = 163840 samples. One CTA = 64 samples, 256 threads.
//   agg -> L1a(32x256) -> L1b(256x256) -> L3a -> L3b -> heads, all in SMEM.
//   Inner GEMM uses packed fma.rn.f32x2 (full-rate fp32 on Blackwell).
// ---------------------------------------------------------------------------

#define TILE_M   64
#define H_DIM    256
#define F_DIM    32
#define K_NB     8
#define LDA      260          // activation row stride in floats (16B aligned, depads banks)
#define BK       32           // K-tile of streamed weights
#define NTHREADS 256

// ---- packed f32x2 helpers --------------------------------------------------
__device__ __forceinline__ unsigned long long dup2(float a) {
    unsigned long long r;
    asm("mov.b64 %0, {%1, %1};" : "=l"(r) : "f"(a));
    return r;
}
__device__ __forceinline__ void fma2(unsigned long long& acc,
                                     unsigned long long a,
                                     unsigned long long b) {
    asm("fma.rn.f32x2 %0, %1, %2, %0;" : "+l"(acc) : "l"(a), "l"(b));
}
__device__ __forceinline__ float2 unpack2(unsigned long long v) {
    float2 f;
    asm("mov.b64 {%0, %1}, %2;" : "=f"(f.x), "=f"(f.y) : "l"(v));
    return f;
}

// ---- one Linear(KDIM -> 256) + ReLU layer on a 64-row SMEM tile ------------
// A: [64][LDA] input activations (cols 0..KDIM-1 valid)
// C: [64][LDA] output activations
// Wbuf: 2 * BK*H_DIM floats of staging SMEM
template <int KDIM>
__device__ __forceinline__ void gemm_layer(const float* __restrict__ W,
                                           const float* __restrict__ bias,
                                           const float* __restrict__ A,
                                           float* __restrict__ C,
                                           float* __restrict__ Wbuf,
                                           int tid) {
    constexpr int T = KDIM / BK;               // # of K-tiles (1 or 8)
    const int tcol = tid & 31;                 // 32 col-threads
    const int trow = tid >> 5;                 // 8 row-threads

    unsigned long long acc[8][4];
    #pragma unroll
    for (int i = 0; i < 8; i++)
        #pragma unroll
        for (int p = 0; p < 4; p++) acc[i][p] = 0ull;

    // stage tile 0
    float4 ldreg[8];
    {
        const float4* Wg = (const float4*)W;
        #pragma unroll
        for (int j = 0; j < 8; j++) ldreg[j] = Wg[j * 256 + tid];
        float4* dst = (float4*)Wbuf;
        #pragma unroll
        for (int j = 0; j < 8; j++) dst[j * 256 + tid] = ldreg[j];
    }
    __syncthreads();

    for (int t = 0; t < T; t++) {
        // prefetch next tile into registers while computing on current one
        if (t + 1 < T) {
            const float4* Wg = (const float4*)(W + (size_t)(t + 1) * BK * H_DIM);
            #pragma unroll
            for (int j = 0; j < 8; j++) ldreg[j] = Wg[j * 256 + tid];
        }
        const float* Wb = Wbuf + (t & 1) * (BK * H_DIM);
        const int kbase = t * BK;

        #pragma unroll 2
        for (int kk = 0; kk < BK; kk += 4) {
            float4 av[8];
            #pragma unroll
            for (int i = 0; i < 8; i++)
                av[i] = *(const float4*)(A + (trow * 8 + i) * LDA + kbase + kk);

            #pragma unroll
            for (int dk = 0; dk < 4; dk++) {
                const float* wrow = Wb + (kk + dk) * H_DIM + (tcol << 2);
                ulonglong2 bq0 = *(const ulonglong2*)(wrow);
                ulonglong2 bq1 = *(const ulonglong2*)(wrow + 128);
                #pragma unroll
                for (int i = 0; i < 8; i++) {
                    float aval = (&av[i].x)[dk];
                    unsigned long long a2 = dup2(aval);
                    fma2(acc[i][0], a2, bq0.x);
                    fma2(acc[i][1], a2, bq0.y);
                    fma2(acc[i][2], a2, bq1.x);
                    fma2(acc[i][3], a2, bq1.y);
                }
            }
        }

        if (t + 1 < T) {
            __syncthreads();   // everyone done reading buf[(t+1)&1] (from iter t-1)
            float4* dst = (float4*)(Wbuf + ((t + 1) & 1) * (BK * H_DIM));
            #pragma unroll
            for (int j = 0; j < 8; j++) dst[j * 256 + tid] = ldreg[j];
            __syncthreads();   // new tile visible before next compute
        }
    }

    // epilogue: bias + relu + store
    float4 bq0 = *(const float4*)(bias + (tcol << 2));
    float4 bq1 = *(const float4*)(bias + 128 + (tcol << 2));
    #pragma unroll
    for (int i = 0; i < 8; i++) {
        const int r = trow * 8 + i;
        float2 v0 = unpack2(acc[i][0]);
        float2 v1 = unpack2(acc[i][1]);
        float2 v2 = unpack2(acc[i][2]);
        float2 v3 = unpack2(acc[i][3]);
        float4 o0 = make_float4(fmaxf(v0.x + bq0.x, 0.f), fmaxf(v0.y + bq0.y, 0.f),
                                fmaxf(v1.x + bq0.z, 0.f), fmaxf(v1.y + bq0.w, 0.f));
        float4 o1 = make_float4(fmaxf(v2.x + bq1.x, 0.f), fmaxf(v2.y + bq1.y, 0.f),
                                fmaxf(v3.x + bq1.z, 0.f), fmaxf(v3.y + bq1.w, 0.f));
        *(float4*)(C + r * LDA + (tcol << 2)) = o0;
        *(float4*)(C + r * LDA + 128 + (tcol << 2)) = o1;
    }
}

// ---------------------------------------------------------------------------
__global__ __launch_bounds__(NTHREADS, 1)
void pa_fused_kernel(const float* __restrict__ emb,      // [N,K,F]
                     const float* __restrict__ dists,    // [N,K,3]
                     const float* __restrict__ vdirs,    // [N,3]
                     const int*   __restrict__ pmask,    // [N,K]
                     const float* __restrict__ W1a, const float* __restrict__ b1a,
                     const float* __restrict__ W1b, const float* __restrict__ b1b,
                     const float* __restrict__ W3a, const float* __restrict__ b3a,
                     const float* __restrict__ W3b, const float* __restrict__ b3b,
                     const float* __restrict__ Wa,  const float* __restrict__ ba,
                     const float* __restrict__ Wc,  const float* __restrict__ bc,
                     float* __restrict__ out, int Nsamp) {
    extern __shared__ float smem[];
    float* bufA = smem;                          // 64*260
    float* bufB = smem + TILE_M * LDA;           // 64*260
    float* Wbuf = smem + 2 * TILE_M * LDA;       // 2*32*256

    const int tid  = threadIdx.x;
    const int base = blockIdx.x * TILE_M;

    // ---- phase 0: neighbor aggregation -> feat[64][32] in bufA -------------
    {
        const int s = tid >> 2;        // sample in tile
        const int q = tid & 3;         // feature quarter (8 channels)
        const int gs = base + s;
        float f0 = 0.f, f1 = 0.f, f2 = 0.f, f3 = 0.f;
        float f4 = 0.f, f5 = 0.f, f6 = 0.f, f7 = 0.f;
        if (gs < Nsamp) {
            float w[K_NB];
            float wsum = 0.f;
            #pragma unroll
            for (int k = 0; k < K_NB; k++) {
                const float* dp = dists + ((size_t)gs * K_NB + k) * 3;
                float dx = dp[0], dy = dp[1], dz = dp[2];
                float d2 = dx * dx + dy * dy + dz * dz;
                float m = (float)pmask[(size_t)gs * K_NB + k];
                float wk = m / fmaxf(d2, 1e-8f);
                w[k] = wk;
                wsum += wk;
            }
            float inv = 1.f / fmaxf(wsum, 1e-8f);
            #pragma unroll
            for (int k = 0; k < K_NB; k++) {
                float wk = w[k] * inv;
                const float4* ep = (const float4*)(emb + ((size_t)gs * K_NB + k) * F_DIM + q * 8);
                float4 e0 = ep[0], e1 = ep[1];
                f0 += wk * e0.x; f1 += wk * e0.y; f2 += wk * e0.z; f3 += wk * e0.w;
                f4 += wk * e1.x; f5 += wk * e1.y; f6 += wk * e1.z; f7 += wk * e1.w;
            }
        }
        *(float4*)(bufA + s * LDA + q * 8)     = make_float4(f0, f1, f2, f3);
        *(float4*)(bufA + s * LDA + q * 8 + 4) = make_float4(f4, f5, f6, f7);
    }
    __syncthreads();

    // ---- MLP trunk ---------------------------------------------------------
    gemm_layer<F_DIM>(W1a, b1a, bufA, bufB, Wbuf, tid);  __syncthreads();
    gemm_layer<H_DIM>(W1b, b1b, bufB, bufA, Wbuf, tid);  __syncthreads();
    gemm_layer<H_DIM>(W3a, b3a, bufA, bufB, Wbuf, tid);  __syncthreads();
    gemm_layer<H_DIM>(W3b, b3b, bufB, bufA, Wbuf, tid);  __syncthreads();
    // final hidden h is in bufA

    // ---- heads: alpha + color ---------------------------------------------
    {
        const int s = tid >> 2;
        const int q = tid & 3;
        const int gs = base + s;

        float aA = 0.f, c0 = 0.f, c1 = 0.f, c2 = 0.f;
        const float* hrow = bufA + s * LDA;
        #pragma unroll 8
        for (int kq = 0; kq < H_DIM / 4; kq++) {
            int k = (kq << 2) + q;                 // bank-conflict-free pattern
            float h = hrow[k];
            aA += h * __ldg(Wa + k);
            const float* wr = Wc + k * 3;
            c0 += h * __ldg(wr + 0);
            c1 += h * __ldg(wr + 1);
            c2 += h * __ldg(wr + 2);
        }
        // reduce across the 4 threads of this sample
        #pragma unroll
        for (int off = 1; off < 4; off <<= 1) {
            aA += __shfl_xor_sync(0xffffffffu, aA, off);
            c0 += __shfl_xor_sync(0xffffffffu, c0, off);
            c1 += __shfl_xor_sync(0xffffffffu, c1, off);
            c2 += __shfl_xor_sync(0xffffffffu, c2, off);
        }

        if (q == 0 && gs < Nsamp) {
            // viewdir positional encoding (4 freqs -> 24 channels)
            const float* vp = vdirs + (size_t)gs * 3;
            float vx = vp[0], vy = vp[1], vz = vp[2];
            float nrm = sqrtf(vx * vx + vy * vy + vz * vz);
            float invn = 1.f / fmaxf(nrm, 1e-8f);
            float vv[3] = {vx * invn, vy * invn, vz * invn};
            float freq = 1.f;
            #pragma unroll
            for (int fi = 0; fi < 4; fi++) {
                #pragma unroll
                for (int d = 0; d < 3; d++) {
                    float ang = vv[d] * freq;
                    float sa = __sinf(ang);
                    float ca = __cosf(ang);
                    const float* ws  = Wc + (size_t)(H_DIM + fi * 6 + d) * 3;
                    const float* wcs = Wc + (size_t)(H_DIM + fi * 6 + 3 + d) * 3;
                    c0 += sa * ws[0] + ca * wcs[0];
                    c1 += sa * ws[1] + ca * wcs[1];
                    c2 += sa * ws[2] + ca * wcs[2];
                }
                freq *= 2.f;
            }
            // alpha: softplus(x + ba - 1)
            float xa = aA + ba[0] - 1.f;
            float alpha = (xa > 20.f) ? xa : log1pf(__expf(xa));
            // color: sigmoid * (1+2e-3) - 1e-3
            c0 += bc[0]; c1 += bc[1]; c2 += bc[2];
            float s0 = 1.f / (1.f + __expf(-c0));
            float s1 = 1.f / (1.f + __expf(-c1));
            float s2 = 1.f / (1.f + __expf(-c2));
            const float sc = 1.f + 2e-3f, sh = 1e-3f;
            *(float4*)(out + (size_t)gs * 4) =
                make_float4(alpha, s0 * sc - sh, s1 * sc - sh, s2 * sc - sh);
        }
    }
}

// ---------------------------------------------------------------------------
extern "C" void kernel_launch(void* const* d_in, const int* in_sizes, int n_in,
                              void* d_out, int out_size) {
    const float* emb   = (const float*)d_in[0];
    const float* dists = (const float*)d_in[1];
    const float* vdirs = (const float*)d_in[2];
    const int*   pmask = (const int*)d_in[3];
    const float* W1a = (const float*)d_in[4];
    const float* b1a = (const float*)d_in[5];
    const float* W1b = (const float*)d_in[6];
    const float* b1b = (const float*)d_in[7];
    const float* W3a = (const float*)d_in[8];
    const float* b3a = (const float*)d_in[9];
    const float* W3b = (const float*)d_in[10];
    const float* b3b = (const float*)d_in[11];
    const float* Wa  = (const float*)d_in[12];
    const float* ba  = (const float*)d_in[13];
    const float* Wc  = (const float*)d_in[14];
    const float* bc  = (const float*)d_in[15];
    float* out = (float*)d_out;

    const int N = in_sizes[0] / (K_NB * F_DIM);   // 163840

    const int smem_bytes = (2 * TILE_M * LDA + 2 * BK * H_DIM) * (int)sizeof(float);
    static int attr_done = 0;
    // attribute set is idempotent and capture-legal; call unconditionally
    cudaFuncSetAttribute(pa_fused_kernel,
                         cudaFuncAttributeMaxDynamicSharedMemorySize, smem_bytes);
    (void)attr_done;

    const int grid = (N + TILE_M - 1) / TILE_M;
    pa_fused_kernel<<<grid, NTHREADS, smem_bytes>>>(
        emb, dists, vdirs, pmask,
        W1a, b1a, W1b, b1b, W3a, b3a, W3b, b3b,
        Wa, ba, Wc, bc, out, N);
}

// round 6
// speedup vs baseline: 1.0875x; 1.0875x over previous
#include <cuda_runtime.h>
#include <cstdint>

// ---------------------------------------------------------------------------
// PointAggregator fused forward, fp32, B=1 R=4096 SR=40 K=8 F=32 H=256
//   N = 163840 samples. One CTA = 64 samples, 256 threads, 2 CTAs/SM.
//   agg -> L1a(32x256) -> L1b(256x256) -> L3a -> L3b -> heads.
//   Single in-place activation buffer + BK=16 double-buffered weights
//   => 99 KB SMEM/CTA => 2 CTAs/SM (16 warps). Inner loop: fma.rn.f32x2.
// ---------------------------------------------------------------------------

#define TILE_M   64
#define H_DIM    256
#define F_DIM    32
#define K_NB     8
#define LDA      260          // activation row stride in floats (16B aligned, bank-depad)
#define BK       16           // K-tile of streamed weights
#define NTHREADS 256

// ---- packed f32x2 helpers --------------------------------------------------
__device__ __forceinline__ unsigned long long dup2(float a) {
    unsigned long long r;
    asm("mov.b64 %0, {%1, %1};" : "=l"(r) : "f"(a));
    return r;
}
__device__ __forceinline__ void fma2(unsigned long long& acc,
                                     unsigned long long a,
                                     unsigned long long b) {
    asm("fma.rn.f32x2 %0, %1, %2, %0;" : "+l"(acc) : "l"(a), "l"(b));
}
__device__ __forceinline__ float2 unpack2(unsigned long long v) {
    float2 f;
    asm("mov.b64 {%0, %1}, %2;" : "=f"(f.x), "=f"(f.y) : "l"(v));
    return f;
}

// ---- one Linear(KDIM -> 256) + ReLU layer, IN PLACE on a 64-row SMEM tile --
// A: [64][LDA] activations (cols 0..KDIM-1 valid); output overwrites cols 0..255
// Wbuf: 2 * BK*H_DIM floats of staging SMEM
template <int KDIM>
__device__ __forceinline__ void gemm_layer(const float* __restrict__ W,
                                           const float* __restrict__ bias,
                                           float* __restrict__ A,
                                           float* __restrict__ Wbuf,
                                           int tid) {
    constexpr int T = KDIM / BK;               // # of K-tiles (2 or 16)
    const int tcol = tid & 31;                 // 32 col-threads
    const int trow = tid >> 5;                 // 8 row-threads

    unsigned long long acc[8][4];
    #pragma unroll
    for (int i = 0; i < 8; i++)
        #pragma unroll
        for (int p = 0; p < 4; p++) acc[i][p] = 0ull;

    // stage tile 0  (BK*H_DIM = 4096 floats = 1024 float4, 4 per thread)
    float4 ldreg[4];
    {
        const float4* Wg = (const float4*)W;
        #pragma unroll
        for (int j = 0; j < 4; j++) ldreg[j] = Wg[j * 256 + tid];
        float4* dst = (float4*)Wbuf;
        #pragma unroll
        for (int j = 0; j < 4; j++) dst[j * 256 + tid] = ldreg[j];
    }
    __syncthreads();

    for (int t = 0; t < T; t++) {
        // prefetch next tile into registers while computing on current one
        if (t + 1 < T) {
            const float4* Wg = (const float4*)(W + (size_t)(t + 1) * BK * H_DIM);
            #pragma unroll
            for (int j = 0; j < 4; j++) ldreg[j] = Wg[j * 256 + tid];
        }
        const float* Wb = Wbuf + (t & 1) * (BK * H_DIM);
        const int kbase = t * BK;

        #pragma unroll
        for (int kk = 0; kk < BK; kk += 2) {
            float2 av[8];
            #pragma unroll
            for (int i = 0; i < 8; i++)
                av[i] = *(const float2*)(A + (trow * 8 + i) * LDA + kbase + kk);

            #pragma unroll
            for (int dk = 0; dk < 2; dk++) {
                const float* wrow = Wb + (kk + dk) * H_DIM + (tcol << 2);
                ulonglong2 bq0 = *(const ulonglong2*)(wrow);
                ulonglong2 bq1 = *(const ulonglong2*)(wrow + 128);
                #pragma unroll
                for (int i = 0; i < 8; i++) {
                    float aval = dk ? av[i].y : av[i].x;
                    unsigned long long a2 = dup2(aval);
                    fma2(acc[i][0], a2, bq0.x);
                    fma2(acc[i][1], a2, bq0.y);
                    fma2(acc[i][2], a2, bq1.x);
                    fma2(acc[i][3], a2, bq1.y);
                }
            }
        }

        if (t + 1 < T) {
            __syncthreads();   // everyone done reading buf[(t+1)&1] (from iter t-1)
            float4* dst = (float4*)(Wbuf + ((t + 1) & 1) * (BK * H_DIM));
            #pragma unroll
            for (int j = 0; j < 4; j++) dst[j * 256 + tid] = ldreg[j];
            __syncthreads();   // new tile visible before next compute
        }
    }

    // all A reads complete in regs -> safe to overwrite A in place
    __syncthreads();

    // epilogue: bias + relu + store (in place)
    float4 bq0 = *(const float4*)(bias + (tcol << 2));
    float4 bq1 = *(const float4*)(bias + 128 + (tcol << 2));
    #pragma unroll
    for (int i = 0; i < 8; i++) {
        const int r = trow * 8 + i;
        float2 v0 = unpack2(acc[i][0]);
        float2 v1 = unpack2(acc[i][1]);
        float2 v2 = unpack2(acc[i][2]);
        float2 v3 = unpack2(acc[i][3]);
        float4 o0 = make_float4(fmaxf(v0.x + bq0.x, 0.f), fmaxf(v0.y + bq0.y, 0.f),
                                fmaxf(v1.x + bq0.z, 0.f), fmaxf(v1.y + bq0.w, 0.f));
        float4 o1 = make_float4(fmaxf(v2.x + bq1.x, 0.f), fmaxf(v2.y + bq1.y, 0.f),
                                fmaxf(v3.x + bq1.z, 0.f), fmaxf(v3.y + bq1.w, 0.f));
        *(float4*)(A + r * LDA + (tcol << 2)) = o0;
        *(float4*)(A + r * LDA + 128 + (tcol << 2)) = o1;
    }
}

// ---------------------------------------------------------------------------
__global__ __launch_bounds__(NTHREADS, 2)
void pa_fused_kernel(const float* __restrict__ emb,      // [N,K,F]
                     const float* __restrict__ dists,    // [N,K,3]
                     const float* __restrict__ vdirs,    // [N,3]
                     const int*   __restrict__ pmask,    // [N,K]
                     const float* __restrict__ W1a, const float* __restrict__ b1a,
                     const float* __restrict__ W1b, const float* __restrict__ b1b,
                     const float* __restrict__ W3a, const float* __restrict__ b3a,
                     const float* __restrict__ W3b, const float* __restrict__ b3b,
                     const float* __restrict__ Wa,  const float* __restrict__ ba,
                     const float* __restrict__ Wc,  const float* __restrict__ bc,
                     float* __restrict__ out, int Nsamp) {
    extern __shared__ float smem[];
    float* act  = smem;                          // 64*260
    float* Wbuf = smem + TILE_M * LDA;           // 2*16*256

    const int tid  = threadIdx.x;
    const int base = blockIdx.x * TILE_M;

    // ---- phase 0: neighbor aggregation -> feat[64][32] in act --------------
    {
        const int s = tid >> 2;        // sample in tile
        const int q = tid & 3;         // feature quarter (8 channels)
        const int gs = base + s;
        float f0 = 0.f, f1 = 0.f, f2 = 0.f, f3 = 0.f;
        float f4 = 0.f, f5 = 0.f, f6 = 0.f, f7 = 0.f;
        if (gs < Nsamp) {
            float w[K_NB];
            float wsum = 0.f;
            #pragma unroll
            for (int k = 0; k < K_NB; k++) {
                const float* dp = dists + ((size_t)gs * K_NB + k) * 3;
                float dx = dp[0], dy = dp[1], dz = dp[2];
                float d2 = dx * dx + dy * dy + dz * dz;
                float m = (float)pmask[(size_t)gs * K_NB + k];
                float wk = m / fmaxf(d2, 1e-8f);
                w[k] = wk;
                wsum += wk;
            }
            float inv = 1.f / fmaxf(wsum, 1e-8f);
            #pragma unroll
            for (int k = 0; k < K_NB; k++) {
                float wk = w[k] * inv;
                const float4* ep = (const float4*)(emb + ((size_t)gs * K_NB + k) * F_DIM + q * 8);
                float4 e0 = ep[0], e1 = ep[1];
                f0 += wk * e0.x; f1 += wk * e0.y; f2 += wk * e0.z; f3 += wk * e0.w;
                f4 += wk * e1.x; f5 += wk * e1.y; f6 += wk * e1.z; f7 += wk * e1.w;
            }
        }
        *(float4*)(act + s * LDA + q * 8)     = make_float4(f0, f1, f2, f3);
        *(float4*)(act + s * LDA + q * 8 + 4) = make_float4(f4, f5, f6, f7);
    }
    __syncthreads();

    // ---- MLP trunk (in-place) ---------------------------------------------
    gemm_layer<F_DIM>(W1a, b1a, act, Wbuf, tid);  __syncthreads();
    gemm_layer<H_DIM>(W1b, b1b, act, Wbuf, tid);  __syncthreads();
    gemm_layer<H_DIM>(W3a, b3a, act, Wbuf, tid);  __syncthreads();
    gemm_layer<H_DIM>(W3b, b3b, act, Wbuf, tid);  __syncthreads();
    // final hidden h is in act

    // ---- heads: alpha + color ---------------------------------------------
    {
        const int s = tid >> 2;
        const int q = tid & 3;
        const int gs = base + s;

        float aA = 0.f, c0 = 0.f, c1 = 0.f, c2 = 0.f;
        const float* hrow = act + s * LDA;
        #pragma unroll 8
        for (int kq = 0; kq < H_DIM / 4; kq++) {
            int k = (kq << 2) + q;                 // bank-conflict-free pattern
            float h = hrow[k];
            aA += h * __ldg(Wa + k);
            const float* wr = Wc + k * 3;
            c0 += h * __ldg(wr + 0);
            c1 += h * __ldg(wr + 1);
            c2 += h * __ldg(wr + 2);
        }
        // reduce across the 4 threads of this sample
        #pragma unroll
        for (int off = 1; off < 4; off <<= 1) {
            aA += __shfl_xor_sync(0xffffffffu, aA, off);
            c0 += __shfl_xor_sync(0xffffffffu, c0, off);
            c1 += __shfl_xor_sync(0xffffffffu, c1, off);
            c2 += __shfl_xor_sync(0xffffffffu, c2, off);
        }

        if (q == 0 && gs < Nsamp) {
            // viewdir positional encoding (4 freqs -> 24 channels)
            const float* vp = vdirs + (size_t)gs * 3;
            float vx = vp[0], vy = vp[1], vz = vp[2];
            float nrm = sqrtf(vx * vx + vy * vy + vz * vz);
            float invn = 1.f / fmaxf(nrm, 1e-8f);
            float vv[3] = {vx * invn, vy * invn, vz * invn};
            float freq = 1.f;
            #pragma unroll
            for (int fi = 0; fi < 4; fi++) {
                #pragma unroll
                for (int d = 0; d < 3; d++) {
                    float ang = vv[d] * freq;
                    float sa = __sinf(ang);
                    float ca = __cosf(ang);
                    const float* ws  = Wc + (size_t)(H_DIM + fi * 6 + d) * 3;
                    const float* wcs = Wc + (size_t)(H_DIM + fi * 6 + 3 + d) * 3;
                    c0 += sa * ws[0] + ca * wcs[0];
                    c1 += sa * ws[1] + ca * wcs[1];
                    c2 += sa * ws[2] + ca * wcs[2];
                }
                freq *= 2.f;
            }
            // alpha: softplus(x + ba - 1)
            float xa = aA + ba[0] - 1.f;
            float alpha = (xa > 20.f) ? xa : log1pf(__expf(xa));
            // color: sigmoid * (1+2e-3) - 1e-3
            c0 += bc[0]; c1 += bc[1]; c2 += bc[2];
            float s0 = 1.f / (1.f + __expf(-c0));
            float s1 = 1.f / (1.f + __expf(-c1));
            float s2 = 1.f / (1.f + __expf(-c2));
            const float sc = 1.f + 2e-3f, sh = 1e-3f;
            *(float4*)(out + (size_t)gs * 4) =
                make_float4(alpha, s0 * sc - sh, s1 * sc - sh, s2 * sc - sh);
        }
    }
}

// ---------------------------------------------------------------------------
extern "C" void kernel_launch(void* const* d_in, const int* in_sizes, int n_in,
                              void* d_out, int out_size) {
    const float* emb   = (const float*)d_in[0];
    const float* dists = (const float*)d_in[1];
    const float* vdirs = (const float*)d_in[2];
    const int*   pmask = (const int*)d_in[3];
    const float* W1a = (const float*)d_in[4];
    const float* b1a = (const float*)d_in[5];
    const float* W1b = (const float*)d_in[6];
    const float* b1b = (const float*)d_in[7];
    const float* W3a = (const float*)d_in[8];
    const float* b3a = (const float*)d_in[9];
    const float* W3b = (const float*)d_in[10];
    const float* b3b = (const float*)d_in[11];
    const float* Wa  = (const float*)d_in[12];
    const float* ba  = (const float*)d_in[13];
    const float* Wc  = (const float*)d_in[14];
    const float* bc  = (const float*)d_in[15];
    float* out = (float*)d_out;

    const int N = in_sizes[0] / (K_NB * F_DIM);   // 163840

    const int smem_bytes = (TILE_M * LDA + 2 * BK * H_DIM) * (int)sizeof(float);
    cudaFuncSetAttribute(pa_fused_kernel,
                         cudaFuncAttributeMaxDynamicSharedMemorySize, smem_bytes);

    const int grid = (N + TILE_M - 1) / TILE_M;
    pa_fused_kernel<<<grid, NTHREADS, smem_bytes>>>(
        emb, dists, vdirs, pmask,
        W1a, b1a, W1b, b1b, W3a, b3a, W3b, b3b,
        Wa, ba, Wc, bc, out, N);
}

// round 12
// speedup vs baseline: 2.6096x; 2.3997x over previous
#include <cuda_runtime.h>
#include <cstdint>

// ---------------------------------------------------------------------------
// PointAggregator fused forward — tf32 mma.sync path (portable sm_80+ PTX).
//   N = 163840, CTA = 64 samples, 256 threads (8 warps), 2 CTAs/SM.
//   Warp tile: M=32 x N=64 (2 x m16 tiles, 8 x n8 tiles), K stepped by 8.
//   act[64][260] in SMEM (tf32-rounded), W streamed in BK=16 chunks into
//   double-buffered SMEM [16][264] (stride 264 => conflict-free B frags).
// ---------------------------------------------------------------------------

#define TILE_M   64
#define H_DIM    256
#define LDA      260
#define LDW      264
#define BK       16
#define NTHREADS 256

static __device__ __forceinline__ uint32_t cvt_tf32(float x) {
    uint32_t r;
    asm("cvt.rna.tf32.f32 %0, %1;" : "=r"(r) : "f"(x));
    return r;
}

static __device__ __forceinline__ void mma8(float* d, const uint32_t* a,
                                            uint32_t b0, uint32_t b1) {
    asm volatile("mma.sync.aligned.m16n8k8.row.col.f32.tf32.tf32.f32 "
                 "{%0,%1,%2,%3}, {%4,%5,%6,%7}, {%8,%9}, {%0,%1,%2,%3};"
                 : "+f"(d[0]), "+f"(d[1]), "+f"(d[2]), "+f"(d[3])
                 : "r"(a[0]), "r"(a[1]), "r"(a[2]), "r"(a[3]),
                   "r"(b0), "r"(b1));
}

// ---- one Linear(K -> 256) + ReLU layer, in place on act[64][LDA] -----------
template <int K, bool CVTOUT>
__device__ __forceinline__ void tc_layer(const float* __restrict__ W,
                                         const float* __restrict__ bias,
                                         float* __restrict__ act,
                                         float* __restrict__ wbuf,
                                         float* __restrict__ bias_s,
                                         int tid) {
    const int lane = tid & 31, wid = tid >> 5;
    const int mw = wid >> 2, nw = wid & 3;      // 2 M-groups x 4 N-groups
    const int g = lane >> 2, t4 = lane & 3;
    const int mbase = mw * 32;
    const int nbase = nw * 64;

    float acc[2][8][4];
    #pragma unroll
    for (int i = 0; i < 2; i++)
        #pragma unroll
        for (int j = 0; j < 8; j++)
            #pragma unroll
            for (int p = 0; p < 4; p++) acc[i][j][p] = 0.f;

    if (tid < 256) bias_s[tid] = bias[tid];

    constexpr int NCH = K / BK;
    float4 ldreg[4];

    // stage chunk 0 (BK*256 floats = 1024 float4, 4 per thread), cvt->tf32
    {
        const float4* Wg = (const float4*)W;
        #pragma unroll
        for (int j = 0; j < 4; j++) ldreg[j] = Wg[j * 256 + tid];
        #pragma unroll
        for (int j = 0; j < 4; j++) {
            int idx = j * 256 + tid;
            int k = idx >> 6, n = (idx & 63) << 2;
            float* dst = wbuf + k * LDW + n;
            dst[0] = __uint_as_float(cvt_tf32(ldreg[j].x));
            dst[1] = __uint_as_float(cvt_tf32(ldreg[j].y));
            dst[2] = __uint_as_float(cvt_tf32(ldreg[j].z));
            dst[3] = __uint_as_float(cvt_tf32(ldreg[j].w));
        }
    }
    __syncthreads();

    for (int c = 0; c < NCH; c++) {
        if (c + 1 < NCH) {
            const float4* Wg = (const float4*)(W + (size_t)(c + 1) * BK * 256);
            #pragma unroll
            for (int j = 0; j < 4; j++) ldreg[j] = Wg[j * 256 + tid];
        }
        const float* Wb = wbuf + (c & 1) * (BK * LDW);
        const int kb = c * BK;

        #pragma unroll
        for (int k8 = 0; k8 < BK / 8; k8++) {
            const int k0 = k8 * 8;
            uint32_t a[2][4];
            #pragma unroll
            for (int i = 0; i < 2; i++) {
                const float* ar0 = act + (mbase + i * 16 + g) * LDA + kb + k0;
                const float* ar1 = act + (mbase + i * 16 + 8 + g) * LDA + kb + k0;
                a[i][0] = __float_as_uint(ar0[t4]);
                a[i][1] = __float_as_uint(ar1[t4]);
                a[i][2] = __float_as_uint(ar0[t4 + 4]);
                a[i][3] = __float_as_uint(ar1[t4 + 4]);
            }
            #pragma unroll
            for (int j = 0; j < 8; j++) {
                uint32_t b0 = __float_as_uint(Wb[(k0 + t4) * LDW + nbase + j * 8 + g]);
                uint32_t b1 = __float_as_uint(Wb[(k0 + t4 + 4) * LDW + nbase + j * 8 + g]);
                mma8(acc[0][j], a[0], b0, b1);
                mma8(acc[1][j], a[1], b0, b1);
            }
        }

        if (c + 1 < NCH) {
            __syncthreads();    // everyone done reading buf[(c+1)&1] from iter c-1
            float* dstbuf = wbuf + ((c + 1) & 1) * (BK * LDW);
            #pragma unroll
            for (int j = 0; j < 4; j++) {
                int idx = j * 256 + tid;
                int k = idx >> 6, n = (idx & 63) << 2;
                float* dst = dstbuf + k * LDW + n;
                dst[0] = __uint_as_float(cvt_tf32(ldreg[j].x));
                dst[1] = __uint_as_float(cvt_tf32(ldreg[j].y));
                dst[2] = __uint_as_float(cvt_tf32(ldreg[j].z));
                dst[3] = __uint_as_float(cvt_tf32(ldreg[j].w));
            }
            __syncthreads();    // new tile visible
        }
    }

    __syncthreads();            // all act reads complete -> safe to overwrite

    // epilogue: bias + relu, in place (tf32-rounded if feeding another mma)
    #pragma unroll
    for (int i = 0; i < 2; i++) {
        const int r0 = mbase + i * 16 + g;
        const int r1 = r0 + 8;
        #pragma unroll
        for (int j = 0; j < 8; j++) {
            const int col = nbase + j * 8 + t4 * 2;
            float bv0 = bias_s[col], bv1 = bias_s[col + 1];
            float v00 = fmaxf(acc[i][j][0] + bv0, 0.f);
            float v01 = fmaxf(acc[i][j][1] + bv1, 0.f);
            float v10 = fmaxf(acc[i][j][2] + bv0, 0.f);
            float v11 = fmaxf(acc[i][j][3] + bv1, 0.f);
            if (CVTOUT) {
                act[r0 * LDA + col]     = __uint_as_float(cvt_tf32(v00));
                act[r0 * LDA + col + 1] = __uint_as_float(cvt_tf32(v01));
                act[r1 * LDA + col]     = __uint_as_float(cvt_tf32(v10));
                act[r1 * LDA + col + 1] = __uint_as_float(cvt_tf32(v11));
            } else {
                act[r0 * LDA + col]     = v00;
                act[r0 * LDA + col + 1] = v01;
                act[r1 * LDA + col]     = v10;
                act[r1 * LDA + col + 1] = v11;
            }
        }
    }
}

// ---------------------------------------------------------------------------
__global__ __launch_bounds__(NTHREADS, 2)
void pa_tc_kernel(const float* __restrict__ emb,      // [N,8,32]
                  const float* __restrict__ dists,    // [N,8,3]
                  const float* __restrict__ vdirs,    // [N,3]
                  const int*   __restrict__ pmask,    // [N,8]
                  const float* __restrict__ W1a, const float* __restrict__ b1a,
                  const float* __restrict__ W1b, const float* __restrict__ b1b,
                  const float* __restrict__ W3a, const float* __restrict__ b3a,
                  const float* __restrict__ W3b, const float* __restrict__ b3b,
                  const float* __restrict__ Wa,  const float* __restrict__ ba,
                  const float* __restrict__ Wc,  const float* __restrict__ bc,
                  float* __restrict__ out, int Nsamp) {
    extern __shared__ float smem[];
    float* act    = smem;                               // 64*260
    float* wbuf   = smem + TILE_M * LDA;                // 2*16*264
    float* bias_s = smem + TILE_M * LDA + 2 * BK * LDW; // 256

    const int tid  = threadIdx.x;
    const int base = blockIdx.x * TILE_M;

    // ---- phase 0: aggregation -> feat[64][32] in act (tf32-rounded) --------
    {
        const int s = tid >> 2;        // sample in tile
        const int q = tid & 3;         // feature quarter
        const int gs = base + s;
        float f[8];
        #pragma unroll
        for (int i = 0; i < 8; i++) f[i] = 0.f;
        if (gs < Nsamp) {
            float w[8], wsum = 0.f;
            #pragma unroll
            for (int k = 0; k < 8; k++) {
                const float* dp = dists + ((size_t)gs * 8 + k) * 3;
                float dx = dp[0], dy = dp[1], dz = dp[2];
                float m = (float)pmask[(size_t)gs * 8 + k];
                float wk = m / fmaxf(dx * dx + dy * dy + dz * dz, 1e-8f);
                w[k] = wk; wsum += wk;
            }
            float inv = 1.f / fmaxf(wsum, 1e-8f);
            #pragma unroll
            for (int k = 0; k < 8; k++) {
                float wk = w[k] * inv;
                const float4* ep = (const float4*)(emb + ((size_t)gs * 8 + k) * 32 + q * 8);
                float4 e0 = ep[0], e1 = ep[1];
                f[0] += wk * e0.x; f[1] += wk * e0.y; f[2] += wk * e0.z; f[3] += wk * e0.w;
                f[4] += wk * e1.x; f[5] += wk * e1.y; f[6] += wk * e1.z; f[7] += wk * e1.w;
            }
        }
        float* fr = act + s * LDA + q * 8;
        #pragma unroll
        for (int i = 0; i < 8; i++) fr[i] = __uint_as_float(cvt_tf32(f[i]));
    }
    __syncthreads();

    // ---- MLP trunk ---------------------------------------------------------
    tc_layer< 32, true >(W1a, b1a, act, wbuf, bias_s, tid);  __syncthreads();
    tc_layer<256, true >(W1b, b1b, act, wbuf, bias_s, tid);  __syncthreads();
    tc_layer<256, true >(W3a, b3a, act, wbuf, bias_s, tid);  __syncthreads();
    tc_layer<256, false>(W3b, b3b, act, wbuf, bias_s, tid);  __syncthreads();
    // final hidden h (plain fp32) in act

    // ---- heads: alpha + color ---------------------------------------------
    {
        const int s = tid >> 2;
        const int q = tid & 3;
        const int gs = base + s;

        float aA = 0.f, c0 = 0.f, c1 = 0.f, c2 = 0.f;
        const float* hrow = act + s * LDA;
        #pragma unroll 8
        for (int kq = 0; kq < H_DIM / 4; kq++) {
            int k = (kq << 2) + q;                 // bank-conflict-free
            float h = hrow[k];
            aA += h * __ldg(Wa + k);
            const float* wr = Wc + k * 3;
            c0 += h * __ldg(wr + 0);
            c1 += h * __ldg(wr + 1);
            c2 += h * __ldg(wr + 2);
        }
        #pragma unroll
        for (int off = 1; off < 4; off <<= 1) {
            aA += __shfl_xor_sync(0xffffffffu, aA, off);
            c0 += __shfl_xor_sync(0xffffffffu, c0, off);
            c1 += __shfl_xor_sync(0xffffffffu, c1, off);
            c2 += __shfl_xor_sync(0xffffffffu, c2, off);
        }

        if (q == 0 && gs < Nsamp) {
            const float* vp = vdirs + (size_t)gs * 3;
            float vx = vp[0], vy = vp[1], vz = vp[2];
            float invn = 1.f / fmaxf(sqrtf(vx * vx + vy * vy + vz * vz), 1e-8f);
            float vv[3] = { vx * invn, vy * invn, vz * invn };
            float freq = 1.f;
            #pragma unroll
            for (int fi = 0; fi < 4; fi++) {
                #pragma unroll
                for (int d = 0; d < 3; d++) {
                    float ang = vv[d] * freq;
                    float sa = __sinf(ang), ca = __cosf(ang);
                    const float* ws  = Wc + (size_t)(H_DIM + fi * 6 + d) * 3;
                    const float* wcs = Wc + (size_t)(H_DIM + fi * 6 + 3 + d) * 3;
                    c0 += sa * ws[0] + ca * wcs[0];
                    c1 += sa * ws[1] + ca * wcs[1];
                    c2 += sa * ws[2] + ca * wcs[2];
                }
                freq *= 2.f;
            }
            float xa = aA + ba[0] - 1.f;
            float alpha = (xa > 20.f) ? xa : log1pf(__expf(xa));
            c0 += bc[0]; c1 += bc[1]; c2 += bc[2];
            float s0 = 1.f / (1.f + __expf(-c0));
            float s1 = 1.f / (1.f + __expf(-c1));
            float s2 = 1.f / (1.f + __expf(-c2));
            const float sc = 1.f + 2e-3f, sh = 1e-3f;
            *(float4*)(out + (size_t)gs * 4) =
                make_float4(alpha, s0 * sc - sh, s1 * sc - sh, s2 * sc - sh);
        }
    }
}

// ---------------------------------------------------------------------------
extern "C" void kernel_launch(void* const* d_in, const int* in_sizes, int n_in,
                              void* d_out, int out_size) {
    const float* emb   = (const float*)d_in[0];
    const float* dists = (const float*)d_in[1];
    const float* vdirs = (const float*)d_in[2];
    const int*   pmask = (const int*)d_in[3];
    const float* W1a = (const float*)d_in[4];
    const float* b1a = (const float*)d_in[5];
    const float* W1b = (const float*)d_in[6];
    const float* b1b = (const float*)d_in[7];
    const float* W3a = (const float*)d_in[8];
    const float* b3a = (const float*)d_in[9];
    const float* W3b = (const float*)d_in[10];
    const float* b3b = (const float*)d_in[11];
    const float* Wa  = (const float*)d_in[12];
    const float* ba  = (const float*)d_in[13];
    const float* Wc  = (const float*)d_in[14];
    const float* bc  = (const float*)d_in[15];
    float* out = (float*)d_out;

    const int N = in_sizes[0] / (8 * 32);   // 163840

    const int smem_bytes = (TILE_M * LDA + 2 * BK * LDW + 256) * (int)sizeof(float);
    cudaFuncSetAttribute(pa_tc_kernel,
                         cudaFuncAttributeMaxDynamicSharedMemorySize, smem_bytes);

    const int grid = (N + TILE_M - 1) / TILE_M;
    pa_tc_kernel<<<grid, NTHREADS, smem_bytes>>>(
        emb, dists, vdirs, pmask,
        W1a, b1a, W1b, b1b, W3a, b3a, W3b, b3b,
        Wa, ba, Wc, bc, out, N);
}

// round 14
// speedup vs baseline: 5.1536x; 1.9749x over previous
#include <cuda_runtime.h>
#include <cstdint>

// ---------------------------------------------------------------------------
// PointAggregator fused forward — bf16 m16n8k16 mma.sync path.
//   N = 163840, CTA = 64 samples, 256 threads (8 warps), 2 CTAs/SM.
//   Weights pre-packed once (kernel 1) to bf16 pairs [k/2][256] in a device
//   global; main kernel streams chunks (BK=32) via cp.async, double-buffered,
//   ONE barrier per chunk. Activations live in SMEM as packed bf16 pairs.
//   Warp tile M=32 x N=64; k16 per mma. fp32 accum; heads in fp32.
// ---------------------------------------------------------------------------

#define TILE_M   64
#define H_DIM    256
#define LDA2     132      // act row stride in 32-bit words (128 data + 4 pad)
#define LDW2     264      // wbuf row stride in words (256 data + 8 pad)
#define BK       32       // K per chunk (=> 16 pair-rows per chunk)
#define NTHREADS 256

// packed-weight global: W1a(16x256=4096) W1b(128x256=32768) W3a W3b
#define W1A_OFF 0
#define W1B_OFF 4096
#define W3A_OFF 36864
#define W3B_OFF 69632
#define WPACK_WORDS 102400
static __device__ uint32_t g_wpack[WPACK_WORDS];

// SMEM word layout
#define SW_ACT   0          // 64*132 = 8448 words
#define SW_WBUF  8448       // 2 * 16*264 = 8448 words
#define SW_BIAS  16896      // 256 words (fp32)
#define SW_TOTAL 17152

static __device__ __forceinline__ uint32_t pack_bf16(float hi, float lo) {
    uint32_t r;
    asm("cvt.rn.bf16x2.f32 %0, %1, %2;" : "=r"(r) : "f"(hi), "f"(lo));
    return r;
}
static __device__ __forceinline__ float bf_lo(uint32_t w) {
    return __uint_as_float(w << 16);
}
static __device__ __forceinline__ float bf_hi(uint32_t w) {
    return __uint_as_float(w & 0xffff0000u);
}
static __device__ __forceinline__ uint32_t smem_u32(const void* p) {
    uint32_t a;
    asm("{ .reg .u64 t; cvta.to.shared.u64 t, %1; cvt.u32.u64 %0, t; }"
        : "=r"(a) : "l"(p));
    return a;
}
static __device__ __forceinline__ void cp16(uint32_t dst, const void* src) {
    asm volatile("cp.async.ca.shared.global [%0], [%1], 16;"
                 :: "r"(dst), "l"(src));
}
#define CP_COMMIT() asm volatile("cp.async.commit_group;" ::: "memory")
#define CP_WAIT0()  asm volatile("cp.async.wait_group 0;" ::: "memory")

static __device__ __forceinline__ void mma16(float* d, const uint32_t* a,
                                             uint32_t b0, uint32_t b1) {
    asm volatile("mma.sync.aligned.m16n8k16.row.col.f32.bf16.bf16.f32 "
                 "{%0,%1,%2,%3}, {%4,%5,%6,%7}, {%8,%9}, {%0,%1,%2,%3};"
                 : "+f"(d[0]), "+f"(d[1]), "+f"(d[2]), "+f"(d[3])
                 : "r"(a[0]), "r"(a[1]), "r"(a[2]), "r"(a[3]),
                   "r"(b0), "r"(b1));
}

// ---------------------------------------------------------------------------
// kernel 1: pack fp32 weights -> bf16 pairs (lo = even k) in g_wpack
__global__ void pack_weights(const float* __restrict__ W1a,
                             const float* __restrict__ W1b,
                             const float* __restrict__ W3a,
                             const float* __restrict__ W3b) {
    int widx = blockIdx.x * blockDim.x + threadIdx.x;
    if (widx >= WPACK_WORDS) return;
    const float* src; int local;
    if      (widx < W1B_OFF) { src = W1a; local = widx; }
    else if (widx < W3A_OFF) { src = W1b; local = widx - W1B_OFF; }
    else if (widx < W3B_OFF) { src = W3a; local = widx - W3A_OFF; }
    else                     { src = W3b; local = widx - W3B_OFF; }
    int p = local >> 8, n = local & 255;
    float e = src[(2 * p) * 256 + n];
    float o = src[(2 * p + 1) * 256 + n];
    g_wpack[widx] = pack_bf16(o, e);
}

// ---- stage one chunk (16 pair-rows x 256 words) via cp.async ---------------
static __device__ __forceinline__ void stage_chunk(uint32_t wbuf_base_b,
                                                   const uint32_t* gsrc,
                                                   int buf, int tid) {
    uint32_t dstb = wbuf_base_b + (uint32_t)(buf * 16 * LDW2) * 4u;
    #pragma unroll
    for (int j = 0; j < 4; j++) {
        int i = j * 256 + tid;          // 16B-unit index, 0..1023
        int r = i >> 6;                 // pair-row 0..15
        int o = (i & 63) * 4;           // word offset in row
        cp16(dstb + (uint32_t)(r * LDW2 + o) * 4u, gsrc + r * 256 + o);
    }
    CP_COMMIT();
}

// ---- one Linear(K -> 256) + ReLU layer, in place on packed act -------------
template <int NCH>
__device__ __forceinline__ void tc_layer(const uint32_t wpack_off,
                                         const float* __restrict__ bias,
                                         uint32_t* __restrict__ actw,
                                         uint32_t* __restrict__ wbufw,
                                         float* __restrict__ bias_s,
                                         uint32_t wbuf_base_b, int tid) {
    const int lane = tid & 31, wid = tid >> 5;
    const int mw = wid >> 2, nw = wid & 3;
    const int g = lane >> 2, t4 = lane & 3;
    const int mbase = mw * 32;
    const int nbase = nw * 64;

    float acc[2][8][4];
    #pragma unroll
    for (int i = 0; i < 2; i++)
        #pragma unroll
        for (int j = 0; j < 8; j++)
            #pragma unroll
            for (int p = 0; p < 4; p++) acc[i][j][p] = 0.f;

    bias_s[tid] = bias[tid];

    const uint32_t* gW = g_wpack + wpack_off;
    stage_chunk(wbuf_base_b, gW, 0, tid);

    for (int c = 0; c < NCH; c++) {
        CP_WAIT0();
        __syncthreads();                 // chunk c visible; buf[(c+1)&1] free
        if (c + 1 < NCH)
            stage_chunk(wbuf_base_b, gW + (c + 1) * 4096, (c + 1) & 1, tid);

        const uint32_t* Wb = wbufw + (c & 1) * (16 * LDW2);
        const int kb2 = c * 16;          // pair-row base into act

        #pragma unroll
        for (int k16 = 0; k16 < 2; k16++) {
            const int kw = kb2 + k16 * 8;
            uint32_t a[2][4];
            #pragma unroll
            for (int i = 0; i < 2; i++) {
                const int r0 = (mbase + i * 16 + g) * LDA2;
                const int r1 = r0 + 8 * LDA2;
                a[i][0] = actw[r0 + kw + t4];
                a[i][1] = actw[r1 + kw + t4];
                a[i][2] = actw[r0 + kw + 4 + t4];
                a[i][3] = actw[r1 + kw + 4 + t4];
            }
            const int lrow = k16 * 8;
            #pragma unroll
            for (int j = 0; j < 8; j++) {
                uint32_t b0 = Wb[(lrow + t4) * LDW2 + nbase + j * 8 + g];
                uint32_t b1 = Wb[(lrow + 4 + t4) * LDW2 + nbase + j * 8 + g];
                mma16(acc[0][j], a[0], b0, b1);
                mma16(acc[1][j], a[1], b0, b1);
            }
        }
    }

    __syncthreads();                     // all act reads done -> overwrite ok

    // epilogue: bias + relu -> packed bf16 pairs, in place
    #pragma unroll
    for (int i = 0; i < 2; i++) {
        const int r0 = mbase + i * 16 + g;
        const int r1 = r0 + 8;
        #pragma unroll
        for (int j = 0; j < 8; j++) {
            const int colw = (nbase >> 1) + j * 4 + t4;   // word index
            const float bv0 = bias_s[2 * colw];
            const float bv1 = bias_s[2 * colw + 1];
            float v00 = fmaxf(acc[i][j][0] + bv0, 0.f);
            float v01 = fmaxf(acc[i][j][1] + bv1, 0.f);
            float v10 = fmaxf(acc[i][j][2] + bv0, 0.f);
            float v11 = fmaxf(acc[i][j][3] + bv1, 0.f);
            actw[r0 * LDA2 + colw] = pack_bf16(v01, v00);
            actw[r1 * LDA2 + colw] = pack_bf16(v11, v10);
        }
    }
}

// ---------------------------------------------------------------------------
__global__ __launch_bounds__(NTHREADS, 2)
void pa_tc_kernel(const float* __restrict__ emb,      // [N,8,32]
                  const float* __restrict__ dists,    // [N,8,3]
                  const float* __restrict__ vdirs,    // [N,3]
                  const int*   __restrict__ pmask,    // [N,8]
                  const float* __restrict__ b1a, const float* __restrict__ b1b,
                  const float* __restrict__ b3a, const float* __restrict__ b3b,
                  const float* __restrict__ Wa,  const float* __restrict__ ba,
                  const float* __restrict__ Wc,  const float* __restrict__ bc,
                  float* __restrict__ out, int Nsamp) {
    extern __shared__ uint32_t smemw[];
    uint32_t* actw   = smemw + SW_ACT;
    uint32_t* wbufw  = smemw + SW_WBUF;
    float*    bias_s = (float*)(smemw + SW_BIAS);
    const uint32_t wbuf_base_b = smem_u32(wbufw);

    const int tid  = threadIdx.x;
    const int base = blockIdx.x * TILE_M;

    // ---- phase 0: aggregation -> packed bf16 feat in act -------------------
    {
        const int s = tid >> 2;        // sample in tile
        const int q = tid & 3;         // feature quarter (8 channels)
        const int gs = base + s;
        float f[8];
        #pragma unroll
        for (int i = 0; i < 8; i++) f[i] = 0.f;
        if (gs < Nsamp) {
            float w[8], wsum = 0.f;
            #pragma unroll
            for (int k = 0; k < 8; k++) {
                const float* dp = dists + ((size_t)gs * 8 + k) * 3;
                float dx = dp[0], dy = dp[1], dz = dp[2];
                float m = (float)pmask[(size_t)gs * 8 + k];
                float wk = m / fmaxf(dx * dx + dy * dy + dz * dz, 1e-8f);
                w[k] = wk; wsum += wk;
            }
            float inv = 1.f / fmaxf(wsum, 1e-8f);
            #pragma unroll
            for (int k = 0; k < 8; k++) {
                float wk = w[k] * inv;
                const float4* ep = (const float4*)(emb + ((size_t)gs * 8 + k) * 32 + q * 8);
                float4 e0 = ep[0], e1 = ep[1];
                f[0] += wk * e0.x; f[1] += wk * e0.y; f[2] += wk * e0.z; f[3] += wk * e0.w;
                f[4] += wk * e1.x; f[5] += wk * e1.y; f[6] += wk * e1.z; f[7] += wk * e1.w;
            }
        }
        #pragma unroll
        for (int i = 0; i < 4; i++)
            actw[s * LDA2 + q * 4 + i] = pack_bf16(f[2 * i + 1], f[2 * i]);
    }
    __syncthreads();

    // ---- MLP trunk (layer0 K=32 -> 1 chunk; others 8 chunks) ---------------
    tc_layer<1>(W1A_OFF, b1a, actw, wbufw, bias_s, wbuf_base_b, tid);
    __syncthreads();
    tc_layer<8>(W1B_OFF, b1b, actw, wbufw, bias_s, wbuf_base_b, tid);
    __syncthreads();
    tc_layer<8>(W3A_OFF, b3a, actw, wbufw, bias_s, wbuf_base_b, tid);
    __syncthreads();
    tc_layer<8>(W3B_OFF, b3b, actw, wbufw, bias_s, wbuf_base_b, tid);
    __syncthreads();
    // final hidden h packed bf16 in actw

    // ---- heads: alpha + color ---------------------------------------------
    {
        const int s = tid >> 2;
        const int q = tid & 3;
        const int gs = base + s;

        float aA = 0.f, c0 = 0.f, c1 = 0.f, c2 = 0.f;
        const uint32_t* hrow = actw + s * LDA2;
        #pragma unroll 4
        for (int i = 0; i < 16; i++) {
            const int wI = i * 4 + q;            // conflict-free pattern
            uint32_t wv = hrow[wI];
            float h0 = bf_lo(wv), h1 = bf_hi(wv);
            const int k = wI * 2;
            aA += h0 * __ldg(Wa + k) + h1 * __ldg(Wa + k + 1);
            const float* wr0 = Wc + (size_t)k * 3;
            c0 += h0 * __ldg(wr0 + 0) + h1 * __ldg(wr0 + 3);
            c1 += h0 * __ldg(wr0 + 1) + h1 * __ldg(wr0 + 4);
            c2 += h0 * __ldg(wr0 + 2) + h1 * __ldg(wr0 + 5);
        }
        #pragma unroll
        for (int off = 1; off < 4; off <<= 1) {
            aA += __shfl_xor_sync(0xffffffffu, aA, off);
            c0 += __shfl_xor_sync(0xffffffffu, c0, off);
            c1 += __shfl_xor_sync(0xffffffffu, c1, off);
            c2 += __shfl_xor_sync(0xffffffffu, c2, off);
        }

        if (q == 0 && gs < Nsamp) {
            const float* vp = vdirs + (size_t)gs * 3;
            float vx = vp[0], vy = vp[1], vz = vp[2];
            float invn = 1.f / fmaxf(sqrtf(vx * vx + vy * vy + vz * vz), 1e-8f);
            float vv[3] = { vx * invn, vy * invn, vz * invn };
            float freq = 1.f;
            #pragma unroll
            for (int fi = 0; fi < 4; fi++) {
                #pragma unroll
                for (int d = 0; d < 3; d++) {
                    float ang = vv[d] * freq;
                    float sa = __sinf(ang), ca = __cosf(ang);
                    const float* ws  = Wc + (size_t)(H_DIM + fi * 6 + d) * 3;
                    const float* wcs = Wc + (size_t)(H_DIM + fi * 6 + 3 + d) * 3;
                    c0 += sa * ws[0] + ca * wcs[0];
                    c1 += sa * ws[1] + ca * wcs[1];
                    c2 += sa * ws[2] + ca * wcs[2];
                }
                freq *= 2.f;
            }
            float xa = aA + ba[0] - 1.f;
            float alpha = (xa > 20.f) ? xa : log1pf(__expf(xa));
            c0 += bc[0]; c1 += bc[1]; c2 += bc[2];
            float s0 = 1.f / (1.f + __expf(-c0));
            float s1 = 1.f / (1.f + __expf(-c1));
            float s2 = 1.f / (1.f + __expf(-c2));
            const float sc = 1.f + 2e-3f, sh = 1e-3f;
            *(float4*)(out + (size_t)gs * 4) =
                make_float4(alpha, s0 * sc - sh, s1 * sc - sh, s2 * sc - sh);
        }
    }
}

// ---------------------------------------------------------------------------
extern "C" void kernel_launch(void* const* d_in, const int* in_sizes, int n_in,
                              void* d_out, int out_size) {
    const float* emb   = (const float*)d_in[0];
    const float* dists = (const float*)d_in[1];
    const float* vdirs = (const float*)d_in[2];
    const int*   pmask = (const int*)d_in[3];
    const float* W1a = (const float*)d_in[4];
    const float* b1a = (const float*)d_in[5];
    const float* W1b = (const float*)d_in[6];
    const float* b1b = (const float*)d_in[7];
    const float* W3a = (const float*)d_in[8];
    const float* b3a = (const float*)d_in[9];
    const float* W3b = (const float*)d_in[10];
    const float* b3b = (const float*)d_in[11];
    const float* Wa  = (const float*)d_in[12];
    const float* ba  = (const float*)d_in[13];
    const float* Wc  = (const float*)d_in[14];
    const float* bc  = (const float*)d_in[15];
    float* out = (float*)d_out;

    const int N = in_sizes[0] / (8 * 32);   // 163840

    pack_weights<<<(WPACK_WORDS + 255) / 256, 256>>>(W1a, W1b, W3a, W3b);

    const int smem_bytes = SW_TOTAL * (int)sizeof(uint32_t);
    cudaFuncSetAttribute(pa_tc_kernel,
                         cudaFuncAttributeMaxDynamicSharedMemorySize, smem_bytes);

    const int grid = (N + TILE_M - 1) / TILE_M;
    pa_tc_kernel<<<grid, NTHREADS, smem_bytes>>>(
        emb, dists, vdirs, pmask,
        b1a, b1b, b3a, b3b,
        Wa, ba, Wc, bc, out, N);
}

// round 17
// speedup vs baseline: 5.4199x; 1.0517x over previous
#include <cuda_runtime.h>
#include <cstdint>

// ---------------------------------------------------------------------------
// PointAggregator fused forward — bf16 m16n8k16 mma.sync, fat warp tiles.
//   N = 163840, CTA = 64 samples, 128 threads (4 warps), 2 CTAs/SM.
//   Warp tile Mw=64 x Nw=64 (4 m16 x 8 n8) => 128 acc regs, B/MAC = 0.0625.
//   Weights pre-packed once to bf16 pairs [k/2][256] in device global;
//   chunks (BK=32) streamed via cp.async, double-buffered, 1 barrier/chunk.
//   Activations in SMEM as packed bf16 pairs. fp32 accum + fp32 heads.
// ---------------------------------------------------------------------------

#define TILE_M   64
#define H_DIM    256
#define LDA2     132      // act row stride in words (128 data + 4 pad)
#define LDW2     264      // wbuf row stride in words (256 data + 8 pad)
#define NTHREADS 128

// packed-weight global: W1a(16x256) W1b(128x256) W3a W3b
#define W1A_OFF 0
#define W1B_OFF 4096
#define W3A_OFF 36864
#define W3B_OFF 69632
#define WPACK_WORDS 102400
static __device__ uint32_t g_wpack[WPACK_WORDS];

// SMEM word layout
#define SW_ACT   0          // 64*132 = 8448 words
#define SW_WBUF  8448       // 2 * 16*264 = 8448 words
#define SW_BIAS  16896      // 256 words (fp32)
#define SW_TOTAL 17152

static __device__ __forceinline__ uint32_t pack_bf16(float hi, float lo) {
    uint32_t r;
    asm("cvt.rn.bf16x2.f32 %0, %1, %2;" : "=r"(r) : "f"(hi), "f"(lo));
    return r;
}
static __device__ __forceinline__ float bf_lo(uint32_t w) {
    return __uint_as_float(w << 16);
}
static __device__ __forceinline__ float bf_hi(uint32_t w) {
    return __uint_as_float(w & 0xffff0000u);
}
static __device__ __forceinline__ uint32_t smem_u32(const void* p) {
    uint32_t a;
    asm("{ .reg .u64 t; cvta.to.shared.u64 t, %1; cvt.u32.u64 %0, t; }"
        : "=r"(a) : "l"(p));
    return a;
}
static __device__ __forceinline__ void cp16(uint32_t dst, const void* src) {
    asm volatile("cp.async.ca.shared.global [%0], [%1], 16;"
                 :: "r"(dst), "l"(src));
}
#define CP_COMMIT() asm volatile("cp.async.commit_group;" ::: "memory")
#define CP_WAIT0()  asm volatile("cp.async.wait_group 0;" ::: "memory")

static __device__ __forceinline__ void mma16(float* d, const uint32_t* a,
                                             uint32_t b0, uint32_t b1) {
    asm volatile("mma.sync.aligned.m16n8k16.row.col.f32.bf16.bf16.f32 "
                 "{%0,%1,%2,%3}, {%4,%5,%6,%7}, {%8,%9}, {%0,%1,%2,%3};"
                 : "+f"(d[0]), "+f"(d[1]), "+f"(d[2]), "+f"(d[3])
                 : "r"(a[0]), "r"(a[1]), "r"(a[2]), "r"(a[3]),
                   "r"(b0), "r"(b1));
}

// ---------------------------------------------------------------------------
// kernel 1: pack fp32 weights -> bf16 pairs (lo = even k) in g_wpack
__global__ void pack_weights(const float* __restrict__ W1a,
                             const float* __restrict__ W1b,
                             const float* __restrict__ W3a,
                             const float* __restrict__ W3b) {
    int widx = blockIdx.x * blockDim.x + threadIdx.x;
    if (widx >= WPACK_WORDS) return;
    const float* src; int local;
    if      (widx < W1B_OFF) { src = W1a; local = widx; }
    else if (widx < W3A_OFF) { src = W1b; local = widx - W1B_OFF; }
    else if (widx < W3B_OFF) { src = W3a; local = widx - W3A_OFF; }
    else                     { src = W3b; local = widx - W3B_OFF; }
    int p = local >> 8, n = local & 255;
    float e = src[(2 * p) * 256 + n];
    float o = src[(2 * p + 1) * 256 + n];
    g_wpack[widx] = pack_bf16(o, e);
}

// ---- stage one chunk (16 pair-rows x 256 words) via cp.async ---------------
static __device__ __forceinline__ void stage_chunk(uint32_t wbuf_base_b,
                                                   const uint32_t* gsrc,
                                                   int buf, int tid) {
    uint32_t dstb = wbuf_base_b + (uint32_t)(buf * 16 * LDW2) * 4u;
    #pragma unroll
    for (int j = 0; j < 8; j++) {
        int i = j * 128 + tid;          // 16B-unit index, 0..1023
        int r = i >> 6;                 // pair-row 0..15
        int o = (i & 63) * 4;           // word offset in row
        cp16(dstb + (uint32_t)(r * LDW2 + o) * 4u, gsrc + r * 256 + o);
    }
    CP_COMMIT();
}

// ---- one Linear(K -> 256) + ReLU layer, in place on packed act -------------
// Warp tile Mw=64 (4 m16), Nw=64 (8 n8). 4 warps cover N=256.
template <int NCH>
__device__ __forceinline__ void tc_layer(const uint32_t wpack_off,
                                         const float* __restrict__ bias,
                                         uint32_t* __restrict__ actw,
                                         uint32_t* __restrict__ wbufw,
                                         float* __restrict__ bias_s,
                                         uint32_t wbuf_base_b, int tid) {
    const int lane = tid & 31, wid = tid >> 5;
    const int g = lane >> 2, t4 = lane & 3;
    const int nbase = wid * 64;

    float acc[4][8][4];
    #pragma unroll
    for (int i = 0; i < 4; i++)
        #pragma unroll
        for (int j = 0; j < 8; j++)
            #pragma unroll
            for (int p = 0; p < 4; p++) acc[i][j][p] = 0.f;

    bias_s[tid] = bias[tid];
    bias_s[tid + 128] = bias[tid + 128];

    const uint32_t* gW = g_wpack + wpack_off;
    stage_chunk(wbuf_base_b, gW, 0, tid);

    for (int c = 0; c < NCH; c++) {
        CP_WAIT0();
        __syncthreads();                 // chunk c visible; buf[(c+1)&1] free
        if (c + 1 < NCH)
            stage_chunk(wbuf_base_b, gW + (c + 1) * 4096, (c + 1) & 1, tid);

        const uint32_t* Wb = wbufw + (c & 1) * (16 * LDW2);
        const int kb2 = c * 16;          // pair-row base into act

        #pragma unroll
        for (int k16 = 0; k16 < 2; k16++) {
            const int kw = kb2 + k16 * 8;
            uint32_t a[4][4];
            #pragma unroll
            for (int i = 0; i < 4; i++) {
                const int r0 = (i * 16 + g) * LDA2;
                const int r1 = r0 + 8 * LDA2;
                a[i][0] = actw[r0 + kw + t4];
                a[i][1] = actw[r1 + kw + t4];
                a[i][2] = actw[r0 + kw + 4 + t4];
                a[i][3] = actw[r1 + kw + 4 + t4];
            }
            const int lrow = k16 * 8;
            #pragma unroll
            for (int j = 0; j < 8; j++) {
                uint32_t b0 = Wb[(lrow + t4) * LDW2 + nbase + j * 8 + g];
                uint32_t b1 = Wb[(lrow + 4 + t4) * LDW2 + nbase + j * 8 + g];
                #pragma unroll
                for (int i = 0; i < 4; i++)
                    mma16(acc[i][j], a[i], b0, b1);
            }
        }
    }

    __syncthreads();                     // all act reads done -> overwrite ok

    // epilogue: bias + relu -> packed bf16 pairs, in place
    #pragma unroll
    for (int i = 0; i < 4; i++) {
        const int r0 = i * 16 + g;
        const int r1 = r0 + 8;
        #pragma unroll
        for (int j = 0; j < 8; j++) {
            const int colw = (nbase >> 1) + j * 4 + t4;   // word index
            const float bv0 = bias_s[2 * colw];
            const float bv1 = bias_s[2 * colw + 1];
            float v00 = fmaxf(acc[i][j][0] + bv0, 0.f);
            float v01 = fmaxf(acc[i][j][1] + bv1, 0.f);
            float v10 = fmaxf(acc[i][j][2] + bv0, 0.f);
            float v11 = fmaxf(acc[i][j][3] + bv1, 0.f);
            actw[r0 * LDA2 + colw] = pack_bf16(v01, v00);
            actw[r1 * LDA2 + colw] = pack_bf16(v11, v10);
        }
    }
}

// ---------------------------------------------------------------------------
__global__ __launch_bounds__(NTHREADS, 2)
void pa_tc_kernel(const float* __restrict__ emb,      // [N,8,32]
                  const float* __restrict__ dists,    // [N,8,3]
                  const float* __restrict__ vdirs,    // [N,3]
                  const int*   __restrict__ pmask,    // [N,8]
                  const float* __restrict__ b1a, const float* __restrict__ b1b,
                  const float* __restrict__ b3a, const float* __restrict__ b3b,
                  const float* __restrict__ Wa,  const float* __restrict__ ba,
                  const float* __restrict__ Wc,  const float* __restrict__ bc,
                  float* __restrict__ out, int Nsamp) {
    extern __shared__ uint32_t smemw[];
    uint32_t* actw   = smemw + SW_ACT;
    uint32_t* wbufw  = smemw + SW_WBUF;
    float*    bias_s = (float*)(smemw + SW_BIAS);
    const uint32_t wbuf_base_b = smem_u32(wbufw);

    const int tid  = threadIdx.x;
    const int base = blockIdx.x * TILE_M;

    // ---- phase 0: aggregation -> packed bf16 feat in act -------------------
    // 2 threads per sample, 16 features (= 8 packed words) each.
    {
        const int s = tid >> 1, half = tid & 1;
        const int gs = base + s;
        float f[16];
        #pragma unroll
        for (int i = 0; i < 16; i++) f[i] = 0.f;
        if (gs < Nsamp) {
            float w[8], wsum = 0.f;
            #pragma unroll
            for (int k = 0; k < 8; k++) {
                const float* dp = dists + ((size_t)gs * 8 + k) * 3;
                float dx = dp[0], dy = dp[1], dz = dp[2];
                float m = (float)pmask[(size_t)gs * 8 + k];
                float wk = m / fmaxf(dx * dx + dy * dy + dz * dz, 1e-8f);
                w[k] = wk; wsum += wk;
            }
            float inv = 1.f / fmaxf(wsum, 1e-8f);
            #pragma unroll
            for (int k = 0; k < 8; k++) {
                float wk = w[k] * inv;
                const float4* ep = (const float4*)(emb + ((size_t)gs * 8 + k) * 32 + half * 16);
                #pragma unroll
                for (int q = 0; q < 4; q++) {
                    float4 e = ep[q];
                    f[q * 4 + 0] += wk * e.x; f[q * 4 + 1] += wk * e.y;
                    f[q * 4 + 2] += wk * e.z; f[q * 4 + 3] += wk * e.w;
                }
            }
        }
        #pragma unroll
        for (int i = 0; i < 8; i++)
            actw[s * LDA2 + half * 8 + i] = pack_bf16(f[2 * i + 1], f[2 * i]);
    }
    __syncthreads();

    // ---- MLP trunk (layer0 K=32 -> 1 chunk; others 8 chunks) ---------------
    tc_layer<1>(W1A_OFF, b1a, actw, wbufw, bias_s, wbuf_base_b, tid);
    __syncthreads();
    tc_layer<8>(W1B_OFF, b1b, actw, wbufw, bias_s, wbuf_base_b, tid);
    __syncthreads();
    tc_layer<8>(W3A_OFF, b3a, actw, wbufw, bias_s, wbuf_base_b, tid);
    __syncthreads();
    tc_layer<8>(W3B_OFF, b3b, actw, wbufw, bias_s, wbuf_base_b, tid);
    __syncthreads();
    // final hidden h packed bf16 in actw

    // ---- heads: alpha + color (2 threads per sample) ------------------------
    {
        const int s = tid >> 1, q = tid & 1;
        const int gs = base + s;

        float aA = 0.f, c0 = 0.f, c1 = 0.f, c2 = 0.f;
        const uint32_t* hrow = actw + s * LDA2;
        #pragma unroll 8
        for (int i = 0; i < 32; i++) {
            const int wI = i * 2 + q;
            uint32_t wv = hrow[wI];
            float h0 = bf_lo(wv), h1 = bf_hi(wv);
            const int k = wI * 2;
            aA += h0 * __ldg(Wa + k) + h1 * __ldg(Wa + k + 1);
            const float* wr0 = Wc + (size_t)k * 3;
            c0 += h0 * __ldg(wr0 + 0) + h1 * __ldg(wr0 + 3);
            c1 += h0 * __ldg(wr0 + 1) + h1 * __ldg(wr0 + 4);
            c2 += h0 * __ldg(wr0 + 2) + h1 * __ldg(wr0 + 5);
        }
        aA += __shfl_xor_sync(0xffffffffu, aA, 1);
        c0 += __shfl_xor_sync(0xffffffffu, c0, 1);
        c1 += __shfl_xor_sync(0xffffffffu, c1, 1);
        c2 += __shfl_xor_sync(0xffffffffu, c2, 1);

        if (q == 0 && gs < Nsamp) {
            const float* vp = vdirs + (size_t)gs * 3;
            float vx = vp[0], vy = vp[1], vz = vp[2];
            float invn = 1.f / fmaxf(sqrtf(vx * vx + vy * vy + vz * vz), 1e-8f);
            float vv[3] = { vx * invn, vy * invn, vz * invn };
            float freq = 1.f;
            #pragma unroll
            for (int fi = 0; fi < 4; fi++) {
                #pragma unroll
                for (int d = 0; d < 3; d++) {
                    float ang = vv[d] * freq;
                    float sa = __sinf(ang), ca = __cosf(ang);
                    const float* ws  = Wc + (size_t)(H_DIM + fi * 6 + d) * 3;
                    const float* wcs = Wc + (size_t)(H_DIM + fi * 6 + 3 + d) * 3;
                    c0 += sa * ws[0] + ca * wcs[0];
                    c1 += sa * ws[1] + ca * wcs[1];
                    c2 += sa * ws[2] + ca * wcs[2];
                }
                freq *= 2.f;
            }
            float xa = aA + ba[0] - 1.f;
            float alpha = (xa > 20.f) ? xa : log1pf(__expf(xa));
            c0 += bc[0]; c1 += bc[1]; c2 += bc[2];
            float s0 = 1.f / (1.f + __expf(-c0));
            float s1 = 1.f / (1.f + __expf(-c1));
            float s2 = 1.f / (1.f + __expf(-c2));
            const float sc = 1.f + 2e-3f, sh = 1e-3f;
            *(float4*)(out + (size_t)gs * 4) =
                make_float4(alpha, s0 * sc - sh, s1 * sc - sh, s2 * sc - sh);
        }
    }
}

// ---------------------------------------------------------------------------
extern "C" void kernel_launch(void* const* d_in, const int* in_sizes, int n_in,
                              void* d_out, int out_size) {
    const float* emb   = (const float*)d_in[0];
    const float* dists = (const float*)d_in[1];
    const float* vdirs = (const float*)d_in[2];
    const int*   pmask = (const int*)d_in[3];
    const float* W1a = (const float*)d_in[4];
    const float* b1a = (const float*)d_in[5];
    const float* W1b = (const float*)d_in[6];
    const float* b1b = (const float*)d_in[7];
    const float* W3a = (const float*)d_in[8];
    const float* b3a = (const float*)d_in[9];
    const float* W3b = (const float*)d_in[10];
    const float* b3b = (const float*)d_in[11];
    const float* Wa  = (const float*)d_in[12];
    const float* ba  = (const float*)d_in[13];
    const float* Wc  = (const float*)d_in[14];
    const float* bc  = (const float*)d_in[15];
    float* out = (float*)d_out;

    const int N = in_sizes[0] / (8 * 32);   // 163840

    pack_weights<<<(WPACK_WORDS + 255) / 256, 256>>>(W1a, W1b, W3a, W3b);

    const int smem_bytes = SW_TOTAL * (int)sizeof(uint32_t);
    cudaFuncSetAttribute(pa_tc_kernel,
                         cudaFuncAttributeMaxDynamicSharedMemorySize, smem_bytes);

    const int grid = (N + TILE_M - 1) / TILE_M;
    pa_tc_kernel<<<grid, NTHREADS, smem_bytes>>>(
        emb, dists, vdirs, pmask,
        b1a, b1b, b3a, b3b,
        Wa, ba, Wc, bc, out, N);
}